// round 11
// baseline (speedup 1.0000x reference)
#include <cuda_runtime.h>

#define BATCH 1024
#define NPTS  128
#define MPTS  128
#define TIME  10

#define MAGIC 12582912.0f            /* 1.5 * 2^23 : round-to-nearest-even shifter */
#define KEYMASK 0xFFFFFF80

// Scratch (no allocation allowed)
__device__ float g_part1[BATCH];
__device__ float g_part2[BATCH];
__device__ float g_part3[BATCH];
__device__ int   g_done[BATCH];            // per-batch arrival counter (self-resetting)
__device__ int   g_k1[2][BATCH * NPTS];    // per-half partial keys, loop1
__device__ int   g_k2[2][BATCH * NPTS];    // per-half partial keys, loop2
__device__ unsigned int g_count = 0;

// ---- f32x2 packed helpers (sm_103a) ----
__device__ __forceinline__ unsigned long long pk2(float a, float b) {
    unsigned long long r;
    asm("mov.b64 %0, {%1, %2};" : "=l"(r) : "f"(a), "f"(b));
    return r;
}
__device__ __forceinline__ float2 upk2(unsigned long long v) {
    float2 r;
    asm("mov.b64 {%0, %1}, %2;" : "=f"(r.x), "=f"(r.y) : "l"(v));
    return r;
}
__device__ __forceinline__ unsigned long long fma2_(unsigned long long a, unsigned long long b, unsigned long long c) {
    unsigned long long d;
    asm("fma.rn.f32x2 %0, %1, %2, %3;" : "=l"(d) : "l"(a), "l"(b), "l"(c));
    return d;
}
__device__ __forceinline__ unsigned long long add2_(unsigned long long a, unsigned long long b) {
    unsigned long long d;
    asm("add.rn.f32x2 %0, %1, %2;" : "=l"(d) : "l"(a), "l"(b));
    return d;
}
__device__ __forceinline__ unsigned long long mul2_(unsigned long long a, unsigned long long b) {
    unsigned long long d;
    asm("mul.rn.f32x2 %0, %1, %2;" : "=l"(d) : "l"(a), "l"(b));
    return d;
}
__device__ __forceinline__ void lds_v2(const void* p, unsigned long long& a, unsigned long long& b) {
    unsigned s = (unsigned)__cvta_generic_to_shared(p);
    asm volatile("ld.shared.v2.b64 {%0, %1}, [%2];" : "=l"(a), "=l"(b) : "r"(s));
}
__device__ __forceinline__ unsigned long long lds_b64(const void* p) {
    unsigned s = (unsigned)__cvta_generic_to_shared(p);
    unsigned long long a;
    asm volatile("ld.shared.b64 %0, [%1];" : "=l"(a) : "r"(s));
    return a;
}

__global__ __launch_bounds__(128, 9)
void dmloss_fused(const float* __restrict__ ini_pred,   // [B,N,2]
                  const float* __restrict__ pred_polys, // [B,N,2]
                  const float* __restrict__ gt_polys,   // [B,M,2]
                  const float* __restrict__ kmask,      // [B,M]
                  float* __restrict__ out)
{
    // pair-interleaved layouts: entry j holds fields for candidates 2j (even) and 2j+1 (odd)
    __shared__ float4 sA[MPTS / 2];   // (ax_e, ax_o, ay_e, ay_o)   a = prev vertex
    __shared__ float4 sB[MPTS / 2];   // (ex5_e, ex5_o, ey5_e, ey5_o)   0.2*e
    __shared__ float4 sC[MPTS / 2];   // (c_e, c_o, e2c_e, e2c_o)   c=-50/e2, e2c=0.01e2
    __shared__ float4 sP[NPTS / 2];   // (qx_e, qx_o, qy_e, qy_o)       ini_pred
    __shared__ float2 sQ[NPTS / 2];   // (qz_e, qz_o)   qz = 0.5|q|^2
    __shared__ float2 s_gt[MPTS];     // current vertex b (epilogue)
    __shared__ float  s_step[TIME];   // exact k/10 (epilogue only)
    __shared__ float  s_r1[4], s_r2[4], s_r3[4];
    __shared__ int    s_sec, s_last;

    const int tid = threadIdx.x;
    const int bh  = blockIdx.x;
    const int b   = bh >> 1;
    const int h   = bh & 1;           // which candidate half this CTA scans
    const int j   = tid >> 1;
    const int e   = tid & 1;

    // ---- setup: full tables in every CTA (epilogue needs any winner) ----
    const float2* gt = (const float2*)(gt_polys + (size_t)b * MPTS * 2);
    const float2 bcur  = gt[tid];
    const float2 aprev = gt[(tid + MPTS - 1) & (MPTS - 1)];
    {
        const float ex  = bcur.x - aprev.x;
        const float ey  = bcur.y - aprev.y;
        const float e2  = ex * ex + ey * ey;
        ((float*)&sA[j])[e]     = aprev.x;
        ((float*)&sA[j])[2 + e] = aprev.y;
        ((float*)&sB[j])[e]     = 0.2f * ex;
        ((float*)&sB[j])[2 + e] = 0.2f * ey;
        ((float*)&sC[j])[e]     = -50.0f / fmaxf(e2, 1e-30f);
        ((float*)&sC[j])[2 + e] = 0.01f * e2;
        s_gt[tid] = bcur;
    }
    const float2* ip = (const float2*)(ini_pred + (size_t)b * NPTS * 2);
    const float2 p = ip[tid];
    ((float*)&sP[j])[e]     = p.x;
    ((float*)&sP[j])[2 + e] = p.y;
    ((float*)&sQ[j])[e]     = 0.5f * fmaf(p.x, p.x, p.y * p.y);
    if (tid < TIME) s_step[tid] = (float)tid / 10.0f;
    __syncthreads();

    const float px = p.x, py = p.y;
    const float gx = bcur.x, gy = bcur.y;
    const float hg = 0.5f * fmaf(gx, gx, gy * gy);

    // packed thread constants
    const unsigned long long npx2 = pk2(-px, -px);
    const unsigned long long npy2 = pk2(-py, -py);
    const unsigned long long ngx2 = pk2(-gx, -gx);
    const unsigned long long ngy2 = pk2(-gy, -gy);
    const unsigned long long hg2  = pk2(hg, hg);
    const unsigned long long M2   = pk2(MAGIC, MAGIC);
    const unsigned long long NM2  = pk2(-MAGIC, -MAGIC);
    const int LOB = __float_as_int(MAGIC);          // bits of MAGIC + 0
    const int HIB = __float_as_int(MAGIC + 9.0f);   // bits of MAGIC + 9

    // parity-split accumulators (ILP); index in low bits keeps first-index ties
    int key1a = 0x7FFFFFFF, key1b = 0x7FFFFFFF;
    int key2a = 0x7FFFFFFF, key2b = 0x7FFFFFFF;

    const int i0 = h << 5;     // this CTA scans pair-indices [i0, i0+32)
    #pragma unroll 4
    for (int ii = 0; ii < 32; ii++) {
        const int i  = i0 + ii;
        const int nE = 2 * i, nO = 2 * i + 1;
        // ---- segment pair (2i, 2i+1): pred -> interp-gt ----
        int kA, kB;
        {
            unsigned long long ax2, ay2, ex2, ey2, c2v, ec2;
            lds_v2(&sA[i], ax2, ay2);
            lds_v2(&sB[i], ex2, ey2);
            lds_v2(&sC[i], c2v, ec2);
            const unsigned long long wx2 = add2_(ax2, npx2);                 // a - p
            const unsigned long long wy2 = add2_(ay2, npy2);
            const unsigned long long wd2 = fma2_(wx2, ex2, mul2_(wy2, ey2)); // 0.2 w.e
            const unsigned long long w22 = fma2_(wx2, wx2, mul2_(wy2, wy2)); // |w|^2
            const unsigned long long t2  = fma2_(wd2, c2v, M2);              // magic-biased minimizer
            const float2 tf = upk2(t2);
            const int tiA = min(max(__float_as_int(tf.x), LOB), HIB);        // clamp k to [0,9]
            const int tiB = min(max(__float_as_int(tf.y), LOB), HIB);
            const unsigned long long kr2 = add2_(pk2(__int_as_float(tiA), __int_as_float(tiB)), NM2);
            const unsigned long long sc2 = fma2_(kr2, fma2_(kr2, ec2, wd2), w22); // dist^2 at sample
            const float2 sf = upk2(sc2);
            kA = (__float_as_int(sf.x) & KEYMASK) | nE;
            kB = (__float_as_int(sf.y) & KEYMASK) | nO;
        }
        // ---- pred pair (2i, 2i+1): gt -> pred ----
        int jA, jB;
        {
            unsigned long long qx2, qy2;
            lds_v2(&sP[i], qx2, qy2);
            const unsigned long long qz2 = lds_b64(&sQ[i]);
            const unsigned long long s2 = add2_(qz2, fma2_(ngx2, qx2, fma2_(ngy2, qy2, hg2))); // 0.5|q-g|^2
            const float2 pf = upk2(s2);
            jA = (__float_as_int(pf.x) & KEYMASK) | nE;
            jB = (__float_as_int(pf.y) & KEYMASK) | nO;
        }
        if (ii & 1) {
            key1b = min(key1b, min(kA, kB));
            key2b = min(key2b, min(jA, jB));
        } else {
            key1a = min(key1a, min(kA, kB));
            key2a = min(key2a, min(jA, jB));
        }
    }
    int key1 = min(key1a, key1b);
    int key2 = min(key2a, key2b);

    // ---- publish partial keys; second-arriving CTA merges and finishes ----
    const int kidx = b * NPTS + tid;
    __stcg(&g_k1[h][kidx], key1);
    __stcg(&g_k2[h][kidx], key2);
    __threadfence();
    __syncthreads();
    if (tid == 0) {
        const int old = atomicAdd(&g_done[b], 1);
        s_sec = (old == 1);
        if (old == 1) g_done[b] = 0;    // reset for next graph replay
    }
    __syncthreads();
    if (!s_sec) return;                  // first CTA retires early

    __threadfence();
    key1 = min(key1, __ldcg(&g_k1[1 - h][kidx]));
    key2 = min(key2, __ldcg(&g_k2[1 - h][kidx]));

    // ---- epilogue: recover winners, compute contributions (reference-form interp) ----
    const float2* pp = (const float2*)(pred_polys + (size_t)b * NPTS * 2);
    float c1, c2, c3;
    {
        const int mh = key1 & 0x7F;
        const int jj = mh >> 1, ee = mh & 1;
        const float ax  = ((float*)&sA[jj])[ee];
        const float ay  = ((float*)&sA[jj])[2 + ee];
        const float ex5 = ((float*)&sB[jj])[ee];
        const float ey5 = ((float*)&sB[jj])[2 + ee];
        const float cm  = ((float*)&sC[jj])[ee];
        // bit-identical recompute of kr for winning segment
        const float wx  = __fadd_rn(ax, -px);
        const float wy  = __fadd_rn(ay, -py);
        const float wd  = fmaf(wx, ex5, __fmul_rn(wy, ey5));
        const float t   = fmaf(wd, cm, MAGIC);
        const int   ti  = min(max(__float_as_int(t), LOB), HIB);
        const float kr  = __fadd_rn(__int_as_float(ti), -MAGIC);
        const int   k   = (int)kr;
        const float tk  = s_step[k];
        const float rt  = 1.0f - tk;
        const float2 bb = s_gt[mh];
        const float qx = bb.x * tk + ax * rt;
        const float qy = bb.y * tk + ay * rt;
        const float2 pv = pp[tid];
        c1 = fabsf(pv.x - qx) + fabsf(pv.y - qy);

        const float2 nearp = pp[key2 & 0x7F];
        const float  mk = kmask[(size_t)b * MPTS + tid];
        c2 = (fabsf(nearp.x - gx) + fabsf(nearp.y - gy)) * mk;
        c3 = 2.0f * mk;
    }

    // ---- reduction: warp shuffles, 4 warp partials ----
    #pragma unroll
    for (int o = 16; o > 0; o >>= 1) {
        c1 += __shfl_down_sync(0xFFFFFFFFu, c1, o);
        c2 += __shfl_down_sync(0xFFFFFFFFu, c2, o);
        c3 += __shfl_down_sync(0xFFFFFFFFu, c3, o);
    }
    const int w = tid >> 5;
    if ((tid & 31) == 0) { s_r1[w] = c1; s_r2[w] = c2; s_r3[w] = c3; }
    __syncthreads();
    if (tid == 0) {
        float a = 0.0f, bsum = 0.0f, cc = 0.0f;
        #pragma unroll
        for (int i = 0; i < 4; i++) { a += s_r1[i]; bsum += s_r2[i]; cc += s_r3[i]; }
        g_part1[b] = a; g_part2[b] = bsum; g_part3[b] = cc;
        __threadfence();
        const unsigned old = atomicAdd(&g_count, 1u);
        s_last = (old == (unsigned)(BATCH - 1)) ? 1 : 0;
    }
    __syncthreads();

    // ---- last finishing CTA: deterministic final reduction ----
    if (s_last) {
        float a = 0.0f, bsum = 0.0f, cc = 0.0f;
        #pragma unroll
        for (int i = tid; i < BATCH; i += 128) {
            a    += g_part1[i];
            bsum += g_part2[i];
            cc   += g_part3[i];
        }
        #pragma unroll
        for (int o = 16; o > 0; o >>= 1) {
            a    += __shfl_down_sync(0xFFFFFFFFu, a, o);
            bsum += __shfl_down_sync(0xFFFFFFFFu, bsum, o);
            cc   += __shfl_down_sync(0xFFFFFFFFu, cc, o);
        }
        if ((tid & 31) == 0) { s_r1[w] = a; s_r2[w] = bsum; s_r3[w] = cc; }
        __syncthreads();
        if (tid == 0) {
            float fa = 0.0f, fb = 0.0f, fc = 0.0f;
            #pragma unroll
            for (int i = 0; i < 4; i++) { fa += s_r1[i]; fb += s_r2[i]; fc += s_r3[i]; }
            const float loss_pred2gt = fa / (float)(BATCH * NPTS * 2);
            const float loss_gt2pred = fb / (fc + 1.0f);
            out[0] = (loss_gt2pred + loss_pred2gt) * 0.5f;
            g_count = 0;   // reset for next graph replay
        }
    }
}

extern "C" void kernel_launch(void* const* d_in, const int* in_sizes, int n_in,
                              void* d_out, int out_size)
{
    const float* ini_pred   = (const float*)d_in[0];
    const float* pred_polys = (const float*)d_in[1];
    const float* gt_polys   = (const float*)d_in[2];
    const float* kmask      = (const float*)d_in[3];
    float* out = (float*)d_out;

    dmloss_fused<<<BATCH * 2, 128>>>(ini_pred, pred_polys, gt_polys, kmask, out);
}

// round 14
// speedup vs baseline: 1.2166x; 1.2166x over previous
#include <cuda_runtime.h>

#define BATCH 1024
#define NPTS  128
#define MPTS  128
#define TIME  10

#define MAGIC 12582912.0f            /* 1.5 * 2^23 : round-to-nearest-even shifter */
#define KEYMASK 0xFFFFFF80

// Scratch (no allocation allowed) + cross-block completion counter
__device__ float g_part1[BATCH];
__device__ float g_part2[BATCH];
__device__ float g_part3[BATCH];
__device__ unsigned int g_count = 0;

// ---- f32x2 packed helpers (sm_103a) ----
__device__ __forceinline__ unsigned long long pk2(float a, float b) {
    unsigned long long r;
    asm("mov.b64 %0, {%1, %2};" : "=l"(r) : "f"(a), "f"(b));
    return r;
}
__device__ __forceinline__ float2 upk2(unsigned long long v) {
    float2 r;
    asm("mov.b64 {%0, %1}, %2;" : "=f"(r.x), "=f"(r.y) : "l"(v));
    return r;
}
__device__ __forceinline__ unsigned long long fma2_(unsigned long long a, unsigned long long b, unsigned long long c) {
    unsigned long long d;
    asm("fma.rn.f32x2 %0, %1, %2, %3;" : "=l"(d) : "l"(a), "l"(b), "l"(c));
    return d;
}
__device__ __forceinline__ unsigned long long add2_(unsigned long long a, unsigned long long b) {
    unsigned long long d;
    asm("add.rn.f32x2 %0, %1, %2;" : "=l"(d) : "l"(a), "l"(b));
    return d;
}
__device__ __forceinline__ unsigned long long mul2_(unsigned long long a, unsigned long long b) {
    unsigned long long d;
    asm("mul.rn.f32x2 %0, %1, %2;" : "=l"(d) : "l"(a), "l"(b));
    return d;
}
__device__ __forceinline__ float rcp_approx(float x) {
    float r;
    asm("rcp.approx.f32 %0, %1;" : "=f"(r) : "f"(x));
    return r;
}
__device__ __forceinline__ void lds_v2(const void* p, unsigned long long& a, unsigned long long& b) {
    unsigned s = (unsigned)__cvta_generic_to_shared(p);
    asm volatile("ld.shared.v2.b64 {%0, %1}, [%2];" : "=l"(a), "=l"(b) : "r"(s));
}
__device__ __forceinline__ unsigned long long lds_b64(const void* p) {
    unsigned s = (unsigned)__cvta_generic_to_shared(p);
    unsigned long long a;
    asm volatile("ld.shared.b64 %0, [%1];" : "=l"(a) : "r"(s));
    return a;
}

__global__ __launch_bounds__(128, 7)
void dmloss_fused(const float* __restrict__ ini_pred,   // [B,N,2]
                  const float* __restrict__ pred_polys, // [B,N,2]
                  const float* __restrict__ gt_polys,   // [B,M,2]
                  const float* __restrict__ kmask,      // [B,M]
                  float* __restrict__ out)
{
    // pair-interleaved layouts: entry j holds fields for candidates 2j (even) and 2j+1 (odd)
    __shared__ float4 sA[MPTS / 2];   // (ax_e, ax_o, ay_e, ay_o)   a = prev vertex
    __shared__ float4 sB[MPTS / 2];   // (ex5_e, ex5_o, ey5_e, ey5_o)   0.2*e
    __shared__ float4 sC[MPTS / 2];   // (c_e, c_o, e2c_e, e2c_o)   c=-50/e2, e2c=0.01e2
    __shared__ float4 sP[NPTS / 2];   // (qx_e, qx_o, qy_e, qy_o)       ini_pred
    __shared__ float2 sQ[NPTS / 2];   // (qz_e, qz_o)   qz = 0.5|q|^2
    __shared__ float2 s_gt[MPTS];     // current vertex b (epilogue)
    __shared__ float  s_step[TIME];   // exact k/10 (epilogue only)
    __shared__ float  s_r1[4], s_r2[4], s_r3[4];
    __shared__ int    s_last;

    const int tid = threadIdx.x;
    const int b   = blockIdx.x;
    const int j   = tid >> 1;
    const int e   = tid & 1;

    // ---- setup (each thread: one segment + one pred point, scattered into pair slots) ----
    const float2* gt = (const float2*)(gt_polys + (size_t)b * MPTS * 2);
    const float2 bcur  = gt[tid];
    const float2 aprev = gt[(tid + MPTS - 1) & (MPTS - 1)];
    {
        const float ex  = bcur.x - aprev.x;
        const float ey  = bcur.y - aprev.y;
        const float e2  = ex * ex + ey * ey;
        ((float*)&sA[j])[e]     = aprev.x;
        ((float*)&sA[j])[2 + e] = aprev.y;
        ((float*)&sB[j])[e]     = 0.2f * ex;
        ((float*)&sB[j])[2 + e] = 0.2f * ey;
        ((float*)&sC[j])[e]     = -50.0f * rcp_approx(fmaxf(e2, 1e-30f));
        ((float*)&sC[j])[2 + e] = 0.01f * e2;
        s_gt[tid] = bcur;
    }
    const float2* ip = (const float2*)(ini_pred + (size_t)b * NPTS * 2);
    const float2 p = ip[tid];
    ((float*)&sP[j])[e]     = p.x;
    ((float*)&sP[j])[2 + e] = p.y;
    ((float*)&sQ[j])[e]     = 0.5f * fmaf(p.x, p.x, p.y * p.y);
    if (tid < TIME) s_step[tid] = (float)tid / 10.0f;

    // prefetch epilogue operands: latency hides under the 64-iteration loop
    const float2* pp = (const float2*)(pred_polys + (size_t)b * NPTS * 2);
    const float2 pv = pp[tid];
    const float  mk = kmask[(size_t)b * MPTS + tid];
    __syncthreads();

    const float px = p.x, py = p.y;
    const float gx = bcur.x, gy = bcur.y;
    const float hg = 0.5f * fmaf(gx, gx, gy * gy);

    // packed thread constants
    const unsigned long long npx2 = pk2(-px, -px);
    const unsigned long long npy2 = pk2(-py, -py);
    const unsigned long long ngx2 = pk2(-gx, -gx);
    const unsigned long long ngy2 = pk2(-gy, -gy);
    const unsigned long long hg2  = pk2(hg, hg);
    const unsigned long long M2   = pk2(MAGIC, MAGIC);
    const unsigned long long NM2  = pk2(-MAGIC, -MAGIC);
    const int LOB = __float_as_int(MAGIC);          // bits of MAGIC + 0
    const int HIB = __float_as_int(MAGIC + 9.0f);   // bits of MAGIC + 9

    // 4 independent min chains; global index in low bits keeps first-index ties
    int key1a = 0x7FFFFFFF, key1b = 0x7FFFFFFF;
    int key2a = 0x7FFFFFFF, key2b = 0x7FFFFFFF;

    #pragma unroll 8
    for (int i = 0; i < 64; i++) {
        const int nE = 2 * i, nO = 2 * i + 1;
        // ---- segment pair (2i, 2i+1): pred -> interp-gt ----
        int kA, kB;
        {
            unsigned long long ax2, ay2, ex2, ey2, c2v, ec2;
            lds_v2(&sA[i], ax2, ay2);
            lds_v2(&sB[i], ex2, ey2);
            lds_v2(&sC[i], c2v, ec2);
            const unsigned long long wx2 = add2_(ax2, npx2);                 // a - p
            const unsigned long long wy2 = add2_(ay2, npy2);
            const unsigned long long wd2 = fma2_(wx2, ex2, mul2_(wy2, ey2)); // 0.2 w.e
            const unsigned long long w22 = fma2_(wx2, wx2, mul2_(wy2, wy2)); // |w|^2
            const unsigned long long t2  = fma2_(wd2, c2v, M2);              // magic-biased minimizer
            const float2 tf = upk2(t2);
            const int tiA = min(max(__float_as_int(tf.x), LOB), HIB);        // clamp k to [0,9]
            const int tiB = min(max(__float_as_int(tf.y), LOB), HIB);
            const unsigned long long kr2 = add2_(pk2(__int_as_float(tiA), __int_as_float(tiB)), NM2);
            const unsigned long long sc2 = fma2_(kr2, fma2_(kr2, ec2, wd2), w22); // dist^2 at sample
            const float2 sf = upk2(sc2);
            kA = (__float_as_int(sf.x) & KEYMASK) | nE;
            kB = (__float_as_int(sf.y) & KEYMASK) | nO;
        }
        // ---- pred pair (2i, 2i+1): gt -> pred ----
        int jA, jB;
        {
            unsigned long long qx2, qy2;
            lds_v2(&sP[i], qx2, qy2);
            const unsigned long long qz2 = lds_b64(&sQ[i]);
            const unsigned long long s2 = add2_(qz2, fma2_(ngx2, qx2, fma2_(ngy2, qy2, hg2))); // 0.5|q-g|^2
            const float2 pf = upk2(s2);
            jA = (__float_as_int(pf.x) & KEYMASK) | nE;
            jB = (__float_as_int(pf.y) & KEYMASK) | nO;
        }
        key1a = min(key1a, kA);
        key1b = min(key1b, kB);
        key2a = min(key2a, jA);
        key2b = min(key2b, jB);
    }
    const int key1 = min(key1a, key1b);
    const int key2 = min(key2a, key2b);

    // ---- epilogue: recover winners, compute contributions (reference-form interp) ----
    float c1, c2, c3;
    {
        const int mh = key1 & 0x7F;
        const int jj = mh >> 1, ee = mh & 1;
        const float ax  = ((float*)&sA[jj])[ee];
        const float ay  = ((float*)&sA[jj])[2 + ee];
        const float ex5 = ((float*)&sB[jj])[ee];
        const float ey5 = ((float*)&sB[jj])[2 + ee];
        const float cm  = ((float*)&sC[jj])[ee];
        // bit-identical recompute of kr for winning segment
        const float wx  = __fadd_rn(ax, -px);
        const float wy  = __fadd_rn(ay, -py);
        const float wd  = fmaf(wx, ex5, __fmul_rn(wy, ey5));
        const float t   = fmaf(wd, cm, MAGIC);
        const int   ti  = min(max(__float_as_int(t), LOB), HIB);
        const float kr  = __fadd_rn(__int_as_float(ti), -MAGIC);
        const int   k   = (int)kr;
        const float tk  = s_step[k];
        const float rt  = 1.0f - tk;
        const float2 bb = s_gt[mh];
        const float qx = bb.x * tk + ax * rt;
        const float qy = bb.y * tk + ay * rt;
        c1 = fabsf(pv.x - qx) + fabsf(pv.y - qy);

        const float2* pp2 = (const float2*)(pred_polys + (size_t)b * NPTS * 2);
        const float2 nearp = pp2[key2 & 0x7F];
        c2 = (fabsf(nearp.x - gx) + fabsf(nearp.y - gy)) * mk;
        c3 = 2.0f * mk;
    }

    // ---- reduction: warp shuffles, 4 warp partials ----
    #pragma unroll
    for (int o = 16; o > 0; o >>= 1) {
        c1 += __shfl_down_sync(0xFFFFFFFFu, c1, o);
        c2 += __shfl_down_sync(0xFFFFFFFFu, c2, o);
        c3 += __shfl_down_sync(0xFFFFFFFFu, c3, o);
    }
    const int w = tid >> 5;
    if ((tid & 31) == 0) { s_r1[w] = c1; s_r2[w] = c2; s_r3[w] = c3; }
    __syncthreads();
    if (tid == 0) {
        float a = 0.0f, bsum = 0.0f, cc = 0.0f;
        #pragma unroll
        for (int i = 0; i < 4; i++) { a += s_r1[i]; bsum += s_r2[i]; cc += s_r3[i]; }
        g_part1[b] = a; g_part2[b] = bsum; g_part3[b] = cc;
        __threadfence();
        const unsigned old = atomicAdd(&g_count, 1u);
        s_last = (old == (unsigned)(BATCH - 1)) ? 1 : 0;
    }
    __syncthreads();

    // ---- last block: deterministic final reduction ----
    if (s_last) {
        float a = 0.0f, bsum = 0.0f, cc = 0.0f;
        #pragma unroll
        for (int i = tid; i < BATCH; i += 128) {
            a    += g_part1[i];
            bsum += g_part2[i];
            cc   += g_part3[i];
        }
        #pragma unroll
        for (int o = 16; o > 0; o >>= 1) {
            a    += __shfl_down_sync(0xFFFFFFFFu, a, o);
            bsum += __shfl_down_sync(0xFFFFFFFFu, bsum, o);
            cc   += __shfl_down_sync(0xFFFFFFFFu, cc, o);
        }
        if ((tid & 31) == 0) { s_r1[w] = a; s_r2[w] = bsum; s_r3[w] = cc; }
        __syncthreads();
        if (tid == 0) {
            float fa = 0.0f, fb = 0.0f, fc = 0.0f;
            #pragma unroll
            for (int i = 0; i < 4; i++) { fa += s_r1[i]; fb += s_r2[i]; fc += s_r3[i]; }
            const float loss_pred2gt = fa / (float)(BATCH * NPTS * 2);
            const float loss_gt2pred = fb / (fc + 1.0f);
            out[0] = (loss_gt2pred + loss_pred2gt) * 0.5f;
            g_count = 0;   // reset for next graph replay
        }
    }
}

extern "C" void kernel_launch(void* const* d_in, const int* in_sizes, int n_in,
                              void* d_out, int out_size)
{
    const float* ini_pred   = (const float*)d_in[0];
    const float* pred_polys = (const float*)d_in[1];
    const float* gt_polys   = (const float*)d_in[2];
    const float* kmask      = (const float*)d_in[3];
    float* out = (float*)d_out;

    dmloss_fused<<<BATCH, 128>>>(ini_pred, pred_polys, gt_polys, kmask, out);
}

// round 17
// speedup vs baseline: 1.2570x; 1.0332x over previous
#include <cuda_runtime.h>

#define BATCH 1024
#define NPTS  128
#define MPTS  128
#define TIME  10

#define MAGIC 12582912.0f            /* 1.5 * 2^23 : round-to-nearest-even shifter */
#define KEYMASK 0xFFFFFF80

// Scratch (no allocation allowed) + cross-block completion counter
__device__ float g_part1[BATCH];
__device__ float g_part2[BATCH];
__device__ float g_part3[BATCH];
__device__ unsigned int g_count = 0;

// ---- f32x2 packed helpers (sm_103a) ----
__device__ __forceinline__ unsigned long long pk2(float a, float b) {
    unsigned long long r;
    asm("mov.b64 %0, {%1, %2};" : "=l"(r) : "f"(a), "f"(b));
    return r;
}
__device__ __forceinline__ float2 upk2(unsigned long long v) {
    float2 r;
    asm("mov.b64 {%0, %1}, %2;" : "=f"(r.x), "=f"(r.y) : "l"(v));
    return r;
}
__device__ __forceinline__ unsigned long long fma2_(unsigned long long a, unsigned long long b, unsigned long long c) {
    unsigned long long d;
    asm("fma.rn.f32x2 %0, %1, %2, %3;" : "=l"(d) : "l"(a), "l"(b), "l"(c));
    return d;
}
__device__ __forceinline__ unsigned long long add2_(unsigned long long a, unsigned long long b) {
    unsigned long long d;
    asm("add.rn.f32x2 %0, %1, %2;" : "=l"(d) : "l"(a), "l"(b));
    return d;
}
__device__ __forceinline__ unsigned long long mul2_(unsigned long long a, unsigned long long b) {
    unsigned long long d;
    asm("mul.rn.f32x2 %0, %1, %2;" : "=l"(d) : "l"(a), "l"(b));
    return d;
}
__device__ __forceinline__ float rcp_approx(float x) {
    float r;
    asm("rcp.approx.f32 %0, %1;" : "=f"(r) : "f"(x));
    return r;
}
__device__ __forceinline__ void lds_v2(const void* p, unsigned long long& a, unsigned long long& b) {
    unsigned s = (unsigned)__cvta_generic_to_shared(p);
    asm volatile("ld.shared.v2.b64 {%0, %1}, [%2];" : "=l"(a), "=l"(b) : "r"(s));
}

__global__ __launch_bounds__(128, 7)
void dmloss_fused(const float* __restrict__ ini_pred,   // [B,N,2]
                  const float* __restrict__ pred_polys, // [B,N,2]
                  const float* __restrict__ gt_polys,   // [B,M,2]
                  const float* __restrict__ kmask,      // [B,M]
                  float* __restrict__ out)
{
    // pair-interleaved layouts: entry j holds fields for candidates 2j (even) and 2j+1 (odd)
    __shared__ float4 sA[MPTS / 2];   // (ax_e, ax_o, ay_e, ay_o)   a = prev vertex
    __shared__ float4 sB[MPTS / 2];   // (ex5_e, ex5_o, ey5_e, ey5_o)   0.2*e
    __shared__ float4 sC[MPTS / 2];   // (c_e, c_o, e2c_e, e2c_o)   c=-50/e2, e2c=0.01e2
    __shared__ float4 sP[NPTS / 2];   // (qx_e, qx_o, qy_e, qy_o)       ini_pred
    __shared__ float2 s_gt[MPTS];     // current vertex b (epilogue)
    __shared__ float  s_step[TIME];   // exact k/10 (epilogue only)
    __shared__ float  s_r1[4], s_r2[4], s_r3[4];
    __shared__ int    s_last;

    const int tid = threadIdx.x;
    const int b   = blockIdx.x;
    const int j   = tid >> 1;
    const int e   = tid & 1;

    // ---- setup (each thread: one segment + one pred point, scattered into pair slots) ----
    const float2* gt = (const float2*)(gt_polys + (size_t)b * MPTS * 2);
    const float2 bcur  = gt[tid];
    const float2 aprev = gt[(tid + MPTS - 1) & (MPTS - 1)];
    {
        const float ex  = bcur.x - aprev.x;
        const float ey  = bcur.y - aprev.y;
        const float e2  = ex * ex + ey * ey;
        ((float*)&sA[j])[e]     = aprev.x;
        ((float*)&sA[j])[2 + e] = aprev.y;
        ((float*)&sB[j])[e]     = 0.2f * ex;
        ((float*)&sB[j])[2 + e] = 0.2f * ey;
        ((float*)&sC[j])[e]     = -50.0f * rcp_approx(fmaxf(e2, 1e-30f));
        ((float*)&sC[j])[2 + e] = 0.01f * e2;
        s_gt[tid] = bcur;
    }
    const float2* ip = (const float2*)(ini_pred + (size_t)b * NPTS * 2);
    const float2 p = ip[tid];
    ((float*)&sP[j])[e]     = p.x;
    ((float*)&sP[j])[2 + e] = p.y;
    if (tid < TIME) s_step[tid] = (float)tid / 10.0f;

    // prefetch epilogue operands: latency hides under the 64-iteration loop
    const float2* pp = (const float2*)(pred_polys + (size_t)b * NPTS * 2);
    const float2 pv = pp[tid];
    const float  mk = kmask[(size_t)b * MPTS + tid];
    __syncthreads();

    const float px = p.x, py = p.y;
    const float gx = bcur.x, gy = bcur.y;

    // packed thread constants
    const unsigned long long npx2 = pk2(-px, -px);
    const unsigned long long npy2 = pk2(-py, -py);
    const unsigned long long ngx2 = pk2(-gx, -gx);
    const unsigned long long ngy2 = pk2(-gy, -gy);
    const unsigned long long M2   = pk2(MAGIC, MAGIC);
    const unsigned long long NM2  = pk2(-MAGIC, -MAGIC);
    const int LOB = __float_as_int(MAGIC);          // bits of MAGIC + 0
    const int HIB = __float_as_int(MAGIC + 9.0f);   // bits of MAGIC + 9

    // 4 independent min chains; key = (score_bits & ~0x7F) | idx
    // (masked low bits carry the exact index; exact ties -> lower idx = first-index semantics)
    int key1a = 0x7FFFFFFF, key1b = 0x7FFFFFFF;
    int key2a = 0x7FFFFFFF, key2b = 0x7FFFFFFF;

    #pragma unroll 8
    for (int i = 0; i < 64; i++) {
        const int nE = 2 * i, nO = 2 * i + 1;
        // ---- segment pair (2i, 2i+1): pred -> interp-gt ----
        int kA, kB;
        {
            unsigned long long ax2, ay2, ex2, ey2, c2v, ec2;
            lds_v2(&sA[i], ax2, ay2);
            lds_v2(&sB[i], ex2, ey2);
            lds_v2(&sC[i], c2v, ec2);
            const unsigned long long wx2 = add2_(ax2, npx2);                 // a - p
            const unsigned long long wy2 = add2_(ay2, npy2);
            const unsigned long long wd2 = fma2_(wx2, ex2, mul2_(wy2, ey2)); // 0.2 w.e
            const unsigned long long w22 = fma2_(wx2, wx2, mul2_(wy2, wy2)); // |w|^2
            const unsigned long long t2  = fma2_(wd2, c2v, M2);              // magic-biased minimizer
            const float2 tf = upk2(t2);
            const int tiA = min(max(__float_as_int(tf.x), LOB), HIB);        // clamp k to [0,9]
            const int tiB = min(max(__float_as_int(tf.y), LOB), HIB);
            const unsigned long long kr2 = add2_(pk2(__int_as_float(tiA), __int_as_float(tiB)), NM2);
            const unsigned long long sc2 = fma2_(kr2, fma2_(kr2, ec2, wd2), w22); // dist^2 at sample
            const float2 sf = upk2(sc2);
            kA = (__float_as_int(sf.x) & KEYMASK) | nE;
            kB = (__float_as_int(sf.y) & KEYMASK) | nO;
        }
        // ---- pred pair (2i, 2i+1): gt -> pred, direct-diff form ----
        int jA, jB;
        {
            unsigned long long qx2, qy2;
            lds_v2(&sP[i], qx2, qy2);
            const unsigned long long dx2 = add2_(qx2, ngx2);                 // q - g
            const unsigned long long dy2 = add2_(qy2, ngy2);
            const unsigned long long s2  = fma2_(dx2, dx2, mul2_(dy2, dy2)); // |q-g|^2
            const float2 pf = upk2(s2);
            jA = (__float_as_int(pf.x) & KEYMASK) | nE;
            jB = (__float_as_int(pf.y) & KEYMASK) | nO;
        }
        key1a = min(key1a, kA);
        key1b = min(key1b, kB);
        key2a = min(key2a, jA);
        key2b = min(key2b, jB);
    }
    const int key1 = min(key1a, key1b);
    const int key2 = min(key2a, key2b);

    // ---- epilogue: recover winners, compute contributions (reference-form interp) ----
    float c1, c2, c3;
    {
        const int mh = key1 & 0x7F;
        const int jj = mh >> 1, ee = mh & 1;
        const float ax  = ((float*)&sA[jj])[ee];
        const float ay  = ((float*)&sA[jj])[2 + ee];
        const float ex5 = ((float*)&sB[jj])[ee];
        const float ey5 = ((float*)&sB[jj])[2 + ee];
        const float cm  = ((float*)&sC[jj])[ee];
        // bit-identical recompute of kr for winning segment
        const float wx  = __fadd_rn(ax, -px);
        const float wy  = __fadd_rn(ay, -py);
        const float wd  = fmaf(wx, ex5, __fmul_rn(wy, ey5));
        const float t   = fmaf(wd, cm, MAGIC);
        const int   ti  = min(max(__float_as_int(t), LOB), HIB);
        const float kr  = __fadd_rn(__int_as_float(ti), -MAGIC);
        const int   k   = (int)kr;
        const float tk  = s_step[k];
        const float rt  = 1.0f - tk;
        const float2 bb = s_gt[mh];
        const float qx = bb.x * tk + ax * rt;
        const float qy = bb.y * tk + ay * rt;
        c1 = fabsf(pv.x - qx) + fabsf(pv.y - qy);

        const float2* pp2 = (const float2*)(pred_polys + (size_t)b * NPTS * 2);
        const float2 nearp = pp2[key2 & 0x7F];
        c2 = (fabsf(nearp.x - gx) + fabsf(nearp.y - gy)) * mk;
        c3 = 2.0f * mk;
    }

    // ---- reduction: warp shuffles, 4 warp partials ----
    #pragma unroll
    for (int o = 16; o > 0; o >>= 1) {
        c1 += __shfl_down_sync(0xFFFFFFFFu, c1, o);
        c2 += __shfl_down_sync(0xFFFFFFFFu, c2, o);
        c3 += __shfl_down_sync(0xFFFFFFFFu, c3, o);
    }
    const int w = tid >> 5;
    if ((tid & 31) == 0) { s_r1[w] = c1; s_r2[w] = c2; s_r3[w] = c3; }
    __syncthreads();
    if (tid == 0) {
        float a = 0.0f, bsum = 0.0f, cc = 0.0f;
        #pragma unroll
        for (int i = 0; i < 4; i++) { a += s_r1[i]; bsum += s_r2[i]; cc += s_r3[i]; }
        g_part1[b] = a; g_part2[b] = bsum; g_part3[b] = cc;
        __threadfence();
        const unsigned old = atomicAdd(&g_count, 1u);
        s_last = (old == (unsigned)(BATCH - 1)) ? 1 : 0;
    }
    __syncthreads();

    // ---- last block: deterministic final reduction ----
    if (s_last) {
        float a = 0.0f, bsum = 0.0f, cc = 0.0f;
        #pragma unroll
        for (int i = tid; i < BATCH; i += 128) {
            a    += g_part1[i];
            bsum += g_part2[i];
            cc   += g_part3[i];
        }
        #pragma unroll
        for (int o = 16; o > 0; o >>= 1) {
            a    += __shfl_down_sync(0xFFFFFFFFu, a, o);
            bsum += __shfl_down_sync(0xFFFFFFFFu, bsum, o);
            cc   += __shfl_down_sync(0xFFFFFFFFu, cc, o);
        }
        if ((tid & 31) == 0) { s_r1[w] = a; s_r2[w] = bsum; s_r3[w] = cc; }
        __syncthreads();
        if (tid == 0) {
            float fa = 0.0f, fb = 0.0f, fc = 0.0f;
            #pragma unroll
            for (int i = 0; i < 4; i++) { fa += s_r1[i]; fb += s_r2[i]; fc += s_r3[i]; }
            const float loss_pred2gt = fa / (float)(BATCH * NPTS * 2);
            const float loss_gt2pred = fb / (fc + 1.0f);
            out[0] = (loss_gt2pred + loss_pred2gt) * 0.5f;
            g_count = 0;   // reset for next graph replay
        }
    }
}

extern "C" void kernel_launch(void* const* d_in, const int* in_sizes, int n_in,
                              void* d_out, int out_size)
{
    const float* ini_pred   = (const float*)d_in[0];
    const float* pred_polys = (const float*)d_in[1];
    const float* gt_polys   = (const float*)d_in[2];
    const float* kmask      = (const float*)d_in[3];
    float* out = (float*)d_out;

    dmloss_fused<<<BATCH, 128>>>(ini_pred, pred_polys, gt_polys, kmask, out);
}